// round 1
// baseline (speedup 1.0000x reference)
#include <cuda_runtime.h>
#include <cstdint>
#include <math.h>

// Problem constants (fixed shapes: inputs (32,64,64,64) f32, weight (512,64) f32)
#define N_TOK    131072      // 32*64*64 tokens
#define KCODES   512
#define DDIM     64
#define TILE_M   128         // tokens per CTA
#define NTHREADS 256
#define NCTAS    (N_TOK / TILE_M)   // 1024
#define OUT_ELEMS (N_TOK * DDIM)    // 8388608

// ---- device scratch (no allocations allowed) ----
__device__ int    g_counts[KCODES];
__device__ float  g_sw[KCODES];
__device__ double g_partial[NCTAS];

// ---- shared memory layout (32-bit word offsets) ----
#define WS_WORDS  (64 * 520)                 // W as [d][code], stride 520 -> conflict-free B frags
#define XS_OFF    (WS_WORDS)                 // 33280
#define XS_WORDS  (TILE_M * 65)              // [token][d], stride 65 -> conflict-free
#define SW_OFF    (XS_OFF + XS_WORDS)        // 41600
#define CANDV_OFF (SW_OFF + KCODES)          // 42112
#define CANDI_OFF (CANDV_OFF + 2 * TILE_M)   // 42368
#define IDX_OFF   (CANDI_OFF + 2 * TILE_M)   // 42624
#define RED_OFF   (IDX_OFF + TILE_M)         // 42752 (byte 171008, 8-aligned)
#define SMEM_WORDS (RED_OFF + 2 * NTHREADS)  // 43264
#define SMEM_BYTES (SMEM_WORDS * 4)          // 173056

__device__ __forceinline__ bool better(float v, int i, float u, int j) {
    return (v < u) || (v == u && i < j);
}

__device__ __forceinline__ void top2_upd(float& v1, int& i1, float& v2, int& i2, float s, int c) {
    if (better(s, c, v1, i1)) { v2 = v1; i2 = i1; v1 = s; i1 = c; }
    else if (better(s, c, v2, i2)) { v2 = s; i2 = c; }
}

__device__ __forceinline__ void top2_merge(float& v1, int& i1, float& v2, int& i2,
                                           float u1, int j1, float u2, int j2) {
    if (better(u1, j1, v1, i1)) {
        float nv2; int ni2;
        if (better(v1, i1, u2, j2)) { nv2 = v1; ni2 = i1; } else { nv2 = u2; ni2 = j2; }
        v1 = u1; i1 = j1; v2 = nv2; i2 = ni2;
    } else if (better(u1, j1, v2, i2)) {
        v2 = u1; i2 = j1;
    }
}

__device__ __forceinline__ void mma_tf32(float& c0, float& c1, float& c2, float& c3,
                                         uint32_t a0, uint32_t a1, uint32_t a2, uint32_t a3,
                                         uint32_t b0, uint32_t b1) {
    asm volatile(
        "mma.sync.aligned.m16n8k8.row.col.f32.tf32.tf32.f32 "
        "{%0,%1,%2,%3}, {%4,%5,%6,%7}, {%8,%9}, {%0,%1,%2,%3};\n"
        : "+f"(c0), "+f"(c1), "+f"(c2), "+f"(c3)
        : "r"(a0), "r"(a1), "r"(a2), "r"(a3), "r"(b0), "r"(b1));
}

__device__ __forceinline__ uint32_t f2tf32(float f) {
    uint32_t u;
    asm("cvt.rna.tf32.f32 %0, %1;" : "=r"(u) : "f"(f));
    return u;
}

// K0: zero counts + exact ||w_k||^2
__global__ void vq_prep(const float* __restrict__ w) {
    int t = threadIdx.x;            // 512 threads
    g_counts[t] = 0;
    const float* r = w + t * DDIM;
    float s = 0.f;
#pragma unroll
    for (int d = 0; d < DDIM; d++) s = fmaf(r[d], r[d], s);
    g_sw[t] = s;
}

// K1: per-128-token tile: tf32 MMA scores -> top-2 -> exact fp32 rescore -> fused output/loss
__global__ void __launch_bounds__(NTHREADS, 1)
vq_main(const float* __restrict__ x, const float* __restrict__ w, float* __restrict__ out) {
    extern __shared__ uint32_t sm[];
    uint32_t* Ws   = sm;                       // tf32 bits, [d][code] stride 520
    float*    Xs   = (float*)(sm + XS_OFF);    // exact fp32, [token][d] stride 65
    float*    sws  = (float*)(sm + SW_OFF);
    float*    candV= (float*)(sm + CANDV_OFF);
    int*      candI= (int*)  (sm + CANDI_OFF);
    int*      idxs = (int*)  (sm + IDX_OFF);
    double*   red  = (double*)(sm + RED_OFF);

    const int tid = threadIdx.x;
    const int T0  = blockIdx.x * TILE_M;
    const int bb  = T0 >> 12;          // batch index (4096 tokens per batch image)
    const int hw0 = T0 & 4095;
    const float* xb = x + (size_t)bb * 262144 + hw0;

    // ---- stage W (tf32-rounded) into smem [d][code] ----
    for (int q = tid; q < KCODES * DDIM; q += NTHREADS) {
        int c = q >> 6, d = q & 63;
        Ws[d * 520 + c] = f2tf32(w[q]);
    }
    // ---- stage X tile (exact fp32) [token][d]; global reads coalesced, smem writes conflict-free
    for (int q = tid; q < TILE_M * DDIM; q += NTHREADS) {
        int d = q >> 7, tl = q & 127;
        Xs[tl * 65 + d] = xb[d * 4096 + tl];
    }
    for (int q = tid; q < KCODES; q += NTHREADS) sws[q] = g_sw[q];
    __syncthreads();

    const int lane = tid & 31, warp = tid >> 5;
    const int g = lane >> 2, tg = lane & 3;
    const int rowTok = warp * 16;       // warp owns 16 tokens

    // ---- A fragments for full K=64 (8 k-steps), converted to tf32 once ----
    uint32_t a[8][4];
#pragma unroll
    for (int ks = 0; ks < 8; ks++) {
        a[ks][0] = f2tf32(Xs[(rowTok + g)     * 65 + ks * 8 + tg]);
        a[ks][1] = f2tf32(Xs[(rowTok + g + 8) * 65 + ks * 8 + tg]);
        a[ks][2] = f2tf32(Xs[(rowTok + g)     * 65 + ks * 8 + tg + 4]);
        a[ks][3] = f2tf32(Xs[(rowTok + g + 8) * 65 + ks * 8 + tg + 4]);
    }

    // running top-2 per owned row (row g and row g+8)
    float v1a = 3.4e38f, v2a = 3.4e38f, v1b = 3.4e38f, v2b = 3.4e38f;
    int   i1a = 0x7fffffff, i2a = 0x7fffffff, i1b = 0x7fffffff, i2b = 0x7fffffff;

    for (int nc = 0; nc < 8; nc++) {            // 64 codes per chunk
        float acc[8][4];
#pragma unroll
        for (int nt = 0; nt < 8; nt++) { acc[nt][0]=0.f; acc[nt][1]=0.f; acc[nt][2]=0.f; acc[nt][3]=0.f; }
        const int c0 = nc * 64;
#pragma unroll
        for (int ks = 0; ks < 8; ks++) {
            const uint32_t* wr = Ws + (ks * 8 + tg) * 520 + c0 + g;
#pragma unroll
            for (int nt = 0; nt < 8; nt++) {
                uint32_t b0 = wr[nt * 8];
                uint32_t b1 = wr[nt * 8 + 2080];    // +4 rows of d (4*520)
                mma_tf32(acc[nt][0], acc[nt][1], acc[nt][2], acc[nt][3],
                         a[ks][0], a[ks][1], a[ks][2], a[ks][3], b0, b1);
            }
        }
        // score = sw - 2*dot  (sx is a per-row constant; ranking identical)
#pragma unroll
        for (int nt = 0; nt < 8; nt++) {
#pragma unroll
            for (int j = 0; j < 2; j++) {
                int c = c0 + nt * 8 + tg * 2 + j;
                float swc = sws[c];
                float s0 = fmaf(-2.f, acc[nt][j],     swc);   // row g
                float s1 = fmaf(-2.f, acc[nt][2 + j], swc);   // row g+8
                top2_upd(v1a, i1a, v2a, i2a, s0, c);
                top2_upd(v1b, i1b, v2b, i2b, s1, c);
            }
        }
    }

    // ---- cross-lane merge over the 4 lanes sharing each row (xor 1, xor 2 over lane%4) ----
#pragma unroll
    for (int m = 1; m <= 2; m <<= 1) {
        float u1 = __shfl_xor_sync(0xffffffffu, v1a, m);
        int   j1 = __shfl_xor_sync(0xffffffffu, i1a, m);
        float u2 = __shfl_xor_sync(0xffffffffu, v2a, m);
        int   j2 = __shfl_xor_sync(0xffffffffu, i2a, m);
        top2_merge(v1a, i1a, v2a, i2a, u1, j1, u2, j2);
        u1 = __shfl_xor_sync(0xffffffffu, v1b, m);
        j1 = __shfl_xor_sync(0xffffffffu, i1b, m);
        u2 = __shfl_xor_sync(0xffffffffu, v2b, m);
        j2 = __shfl_xor_sync(0xffffffffu, i2b, m);
        top2_merge(v1b, i1b, v2b, i2b, u1, j1, u2, j2);
    }
    if (tg == 0) {
        int ta = rowTok + g, tb = rowTok + g + 8;
        candV[ta * 2] = v1a; candI[ta * 2] = i1a; candV[ta * 2 + 1] = v2a; candI[ta * 2 + 1] = i2a;
        candV[tb * 2] = v1b; candI[tb * 2] = i1b; candV[tb * 2 + 1] = v2b; candI[tb * 2 + 1] = i2b;
    }
    __syncthreads();

    // ---- exact fp32 rescore of the two candidates per token (replicates reference formula) ----
    {
        int t = tid >> 1, slot = tid & 1;
        int c = candI[t * 2 + slot];
        const float* wr = w + c * DDIM;    // exact fp32 weights (L2-hot)
        float sx = 0.f, dot = 0.f;
#pragma unroll
        for (int d = 0; d < DDIM; d++) {
            float xv = Xs[t * 65 + d];
            sx  = fmaf(xv, xv, sx);
            dot = fmaf(xv, wr[d], dot);
        }
        // dist = (sx - 2*dot) + sw  with explicit rounding like the reference expression
        float dist = __fadd_rn(__fadd_rn(sx, -__fmul_rn(2.f, dot)), sws[c]);
        float dOth = __shfl_xor_sync(0xffffffffu, dist, 1);
        int   cOth = __shfl_xor_sync(0xffffffffu, c, 1);
        if (slot == 0) {
            int pick = better(dist, c, dOth, cOth) ? c : cOth;
            idxs[t] = pick;
            atomicAdd(&g_counts[pick], 1);   // integer atomics: deterministic
        }
    }
    __syncthreads();

    // ---- fused epilogue: out[p] = x[p] + (W[idx[p>>6]][p&63] - x[p]); accumulate mse ----
    {
        size_t base4 = (size_t)T0 * 16;                    // (T0*64)/4 float4s
        const float4* xin4 = (const float4*)x + base4;
        float4*       out4 = (float4*)out + base4;
        double accD = 0.0;
#pragma unroll
        for (int it = 0; it < 8; it++) {
            int q4 = it * NTHREADS + tid;                  // 0..2047
            int tl = q4 >> 4;                              // local token
            int dq = q4 & 15;                              // float4 index within row
            int c  = idxs[tl];
            float4 xv = xin4[q4];
            float4 wv = ((const float4*)(w + c * DDIM))[dq];
            float d0 = wv.x - xv.x, d1 = wv.y - xv.y, d2 = wv.z - xv.z, d3 = wv.w - xv.w;
            float4 r;
            r.x = xv.x + d0; r.y = xv.y + d1; r.z = xv.z + d2; r.w = xv.w + d3;
            out4[q4] = r;
            accD += (double)d0 * d0 + (double)d1 * d1 + (double)d2 * d2 + (double)d3 * d3;
        }
        red[tid] = accD;
        __syncthreads();
        for (int s = NTHREADS / 2; s > 0; s >>= 1) {
            if (tid < s) red[tid] += red[tid + s];
            __syncthreads();
        }
        if (tid == 0) g_partial[blockIdx.x] = red[0];      // deterministic per-CTA partial
    }
}

// K3: reduce partials -> loss; counts -> perplexity (deterministic fixed-order trees)
__global__ void vq_final(float* __restrict__ out, int out_size) {
    __shared__ double sA[NTHREADS];
    __shared__ double sB[NTHREADS];
    int t = threadIdx.x;
    double a = 0.0;
    for (int i = t; i < NCTAS; i += NTHREADS) a += g_partial[i];
    double b = 0.0;
    for (int i = t; i < KCODES; i += NTHREADS) {
        double p = (double)g_counts[i] / (double)N_TOK;
        b += p * log(p + 1e-10);
    }
    sA[t] = a; sB[t] = b;
    __syncthreads();
    for (int s = NTHREADS / 2; s > 0; s >>= 1) {
        if (t < s) { sA[t] += sA[t + s]; sB[t] += sB[t + s]; }
        __syncthreads();
    }
    if (t == 0) {
        double mse  = sA[0] / (double)OUT_ELEMS;
        double loss = mse + 0.25 * mse;
        double perp = exp(-sB[0]);
        if (out_size > OUT_ELEMS)     out[OUT_ELEMS]     = (float)loss;
        if (out_size > OUT_ELEMS + 1) out[OUT_ELEMS + 1] = (float)perp;
    }
}

extern "C" void kernel_launch(void* const* d_in, const int* in_sizes, int n_in,
                              void* d_out, int out_size) {
    const float* x = (const float*)d_in[0];   // inputs (32,64,64,64) f32
    const float* w = (const float*)d_in[1];   // weight (512,64) f32
    float* out = (float*)d_out;

    cudaFuncSetAttribute(vq_main, cudaFuncAttributeMaxDynamicSharedMemorySize, SMEM_BYTES);

    vq_prep<<<1, KCODES>>>(w);
    vq_main<<<NCTAS, NTHREADS, SMEM_BYTES>>>(x, w, out);
    vq_final<<<1, NTHREADS>>>(out, out_size);
}

// round 2
// speedup vs baseline: 3.0942x; 3.0942x over previous
#include <cuda_runtime.h>
#include <cstdint>
#include <math.h>

// Fixed shapes: inputs (32,64,64,64) f32, weight (512,64) f32
#define N_TOK    131072
#define KCODES   512
#define DDIM     64
#define TILE_M   128
#define NTHREADS 256
#define NCTAS    152                 // GB300 has 152 SMs -> one persistent CTA per SM
#define NTILES_T (N_TOK / TILE_M)    // 1024 tiles total
#define OUT_ELEMS (N_TOK * DDIM)

// ---- device scratch ----
__device__ int    g_counts[KCODES];
__device__ float  g_sw[KCODES];
__device__ double g_partial[NCTAS];

// ---- shared memory layout (32-bit word offsets) ----
#define WS_WORDS  (64 * 520)                  // W tf32 [d][code] stride 520 (conflict-free B frags)
#define XS0_OFF   (WS_WORDS)                  // 33280
#define XS_WORDS  (TILE_M * 65)               // 8320, [token][d] stride 65 (conflict-free frags)
#define XS1_OFF   (XS0_OFF + XS_WORDS)        // 41600
#define SW_OFF    (XS1_OFF + XS_WORDS)        // 49920
#define CANDV_OFF (SW_OFF + KCODES)           // 50432
#define CANDI_OFF (CANDV_OFF + 2 * TILE_M)    // 50688
#define IDX_OFF   (CANDI_OFF + 2 * TILE_M)    // 50944
#define RED_OFF   (IDX_OFF + TILE_M)          // 51072 (byte 204288, 8-aligned)
#define SMEM_WORDS (RED_OFF + 2 * NTHREADS)   // 51584
#define SMEM_BYTES (SMEM_WORDS * 4)           // 206336

__device__ __forceinline__ bool better(float v, int i, float u, int j) {
    return (v < u) || (v == u && i < j);
}

// branchless streaming top-2 (no index tiebreak in approx phase; exact rescore resolves)
__device__ __forceinline__ void top2_upd(float& v1, int& i1, float& v2, int& i2, float s, int c) {
    bool b1 = s < v1;
    bool b2 = s < v2;
    float nv2 = b1 ? v1 : (b2 ? s : v2);
    int   ni2 = b1 ? i1 : (b2 ? c : i2);
    v2 = nv2; i2 = ni2;
    v1 = b1 ? s : v1;
    i1 = b1 ? c : i1;
}

__device__ __forceinline__ void mma_tf32(float& c0, float& c1, float& c2, float& c3,
                                         uint32_t a0, uint32_t a1, uint32_t a2, uint32_t a3,
                                         uint32_t b0, uint32_t b1) {
    asm volatile(
        "mma.sync.aligned.m16n8k8.row.col.f32.tf32.tf32.f32 "
        "{%0,%1,%2,%3}, {%4,%5,%6,%7}, {%8,%9}, {%0,%1,%2,%3};\n"
        : "+f"(c0), "+f"(c1), "+f"(c2), "+f"(c3)
        : "r"(a0), "r"(a1), "r"(a2), "r"(a3), "r"(b0), "r"(b1));
}

__device__ __forceinline__ uint32_t f2tf32(float f) {
    uint32_t u;
    asm("cvt.rna.tf32.f32 %0, %1;" : "=r"(u) : "f"(f));
    return u;
}

__device__ __forceinline__ void cp_async4(uint32_t dst_smem, const float* src) {
    asm volatile("cp.async.ca.shared.global [%0], [%1], 4;\n"
                 :: "r"(dst_smem), "l"(src) : "memory");
}

// K0: zero counts + exact ||w_k||^2 (warp per row, float2 loads + shfl reduce)
__global__ void vq_prep(const float* __restrict__ w) {
    int tid  = threadIdx.x;
    int gtid = blockIdx.x * blockDim.x + tid;
    if (gtid < KCODES) g_counts[gtid] = 0;
    int gw   = blockIdx.x * 8 + (tid >> 5);   // global warp 0..127
    int lane = tid & 31;
#pragma unroll
    for (int r = 0; r < 4; r++) {
        int row = gw * 4 + r;                  // 0..511
        float2 v = ((const float2*)(w + row * DDIM))[lane];
        float s = fmaf(v.x, v.x, v.y * v.y);
#pragma unroll
        for (int m = 16; m > 0; m >>= 1) s += __shfl_xor_sync(0xffffffffu, s, m);
        if (lane == 0) g_sw[row] = s;
    }
}

// K1: persistent per-SM kernel. W staged once; X double-buffered via cp.async.
__global__ void __launch_bounds__(NTHREADS, 1)
vq_main(const float* __restrict__ x, const float* __restrict__ w, float* __restrict__ out) {
    extern __shared__ uint32_t sm[];
    uint32_t* Ws    = sm;
    float*    sws   = (float*)(sm + SW_OFF);
    float*    candV = (float*)(sm + CANDV_OFF);
    int*      candI = (int*)  (sm + CANDI_OFF);
    int*      idxs  = (int*)  (sm + IDX_OFF);
    double*   red   = (double*)(sm + RED_OFF);

    const int tid = threadIdx.x;
    const int bid = blockIdx.x;
    const int lane = tid & 31, warp = tid >> 5;
    const int g = lane >> 2, tg = lane & 3;
    const int rowTok = warp * 16;

    // ---- stage W (tf32) once: [d][code] stride 520 ----
    for (int q = tid; q < KCODES * DDIM; q += NTHREADS) {
        int c = q >> 6, d = q & 63;
        Ws[d * 520 + c] = f2tf32(w[q]);
    }
    for (int q = tid; q < KCODES; q += NTHREADS) sws[q] = g_sw[q];

    const int ntiles = (NTILES_T - bid + NCTAS - 1) / NCTAS;

    // ---- prefetch tile 0 ----
    {
        int tile = bid;
        int T0 = tile * TILE_M;
        const float* xb = x + (size_t)(T0 >> 12) * 262144 + (T0 & 4095);
        uint32_t xs = (uint32_t)__cvta_generic_to_shared(sm + XS0_OFF);
#pragma unroll
        for (int it = 0; it < 32; it++) {
            int q = it * NTHREADS + tid;
            int d = q >> 7, tl = q & 127;
            cp_async4(xs + (uint32_t)(tl * 65 + d) * 4u, xb + d * 4096 + tl);
        }
        asm volatile("cp.async.commit_group;\n" ::: "memory");
    }

    double accD = 0.0;   // per-thread loss partial across all tiles (deterministic order)

    for (int j = 0; j < ntiles; j++) {
        const int tile = bid + j * NCTAS;
        const int T0 = tile * TILE_M;
        float* Xs = (float*)(sm + ((j & 1) ? XS1_OFF : XS0_OFF));

        asm volatile("cp.async.wait_group 0;\n" ::: "memory");
        __syncthreads();   // X ready; also fences W staging (j==0) and last tile's smem reads

        // prefetch next tile into other buffer (overlaps with MMA below)
        if (j + 1 < ntiles) {
            int nt = bid + (j + 1) * NCTAS;
            int nT0 = nt * TILE_M;
            const float* xb = x + (size_t)(nT0 >> 12) * 262144 + (nT0 & 4095);
            uint32_t xsn = (uint32_t)__cvta_generic_to_shared(
                sm + (((j + 1) & 1) ? XS1_OFF : XS0_OFF));
#pragma unroll
            for (int it = 0; it < 32; it++) {
                int q = it * NTHREADS + tid;
                int d = q >> 7, tl = q & 127;
                cp_async4(xsn + (uint32_t)(tl * 65 + d) * 4u, xb + d * 4096 + tl);
            }
            asm volatile("cp.async.commit_group;\n" ::: "memory");
        }

        // ---- A fragments (tf32) for 8 k-steps ----
        uint32_t a[8][4];
#pragma unroll
        for (int ks = 0; ks < 8; ks++) {
            a[ks][0] = f2tf32(Xs[(rowTok + g)     * 65 + ks * 8 + tg]);
            a[ks][1] = f2tf32(Xs[(rowTok + g + 8) * 65 + ks * 8 + tg]);
            a[ks][2] = f2tf32(Xs[(rowTok + g)     * 65 + ks * 8 + tg + 4]);
            a[ks][3] = f2tf32(Xs[(rowTok + g + 8) * 65 + ks * 8 + tg + 4]);
        }

        float v1a = 3.4e38f, v2a = 3.4e38f, v1b = 3.4e38f, v2b = 3.4e38f;
        int   i1a = 0, i2a = 0, i1b = 0, i2b = 0;

        for (int nc = 0; nc < 8; nc++) {
            float acc[8][4];
#pragma unroll
            for (int nt = 0; nt < 8; nt++) { acc[nt][0]=0.f; acc[nt][1]=0.f; acc[nt][2]=0.f; acc[nt][3]=0.f; }
            const int c0 = nc * 64;
#pragma unroll
            for (int ks = 0; ks < 8; ks++) {
                const uint32_t* wr = Ws + (ks * 8 + tg) * 520 + c0 + g;
#pragma unroll
                for (int nt = 0; nt < 8; nt++) {
                    uint32_t b0 = wr[nt * 8];
                    uint32_t b1 = wr[nt * 8 + 2080];
                    mma_tf32(acc[nt][0], acc[nt][1], acc[nt][2], acc[nt][3],
                             a[ks][0], a[ks][1], a[ks][2], a[ks][3], b0, b1);
                }
            }
#pragma unroll
            for (int nt = 0; nt < 8; nt++) {
#pragma unroll
                for (int jj = 0; jj < 2; jj++) {
                    int c = c0 + nt * 8 + tg * 2 + jj;
                    float swc = sws[c];
                    float s0 = fmaf(-2.f, acc[nt][jj],     swc);
                    float s1 = fmaf(-2.f, acc[nt][2 + jj], swc);
                    top2_upd(v1a, i1a, v2a, i2a, s0, c);
                    top2_upd(v1b, i1b, v2b, i2b, s1, c);
                }
            }
        }

        // cross-lane merge over the 4 lanes sharing a row
#pragma unroll
        for (int m = 1; m <= 2; m <<= 1) {
            float u1 = __shfl_xor_sync(0xffffffffu, v1a, m);
            int   j1 = __shfl_xor_sync(0xffffffffu, i1a, m);
            float u2 = __shfl_xor_sync(0xffffffffu, v2a, m);
            int   j2 = __shfl_xor_sync(0xffffffffu, i2a, m);
            top2_upd(v1a, i1a, v2a, i2a, u1, j1);
            top2_upd(v1a, i1a, v2a, i2a, u2, j2);
            u1 = __shfl_xor_sync(0xffffffffu, v1b, m);
            j1 = __shfl_xor_sync(0xffffffffu, i1b, m);
            u2 = __shfl_xor_sync(0xffffffffu, v2b, m);
            j2 = __shfl_xor_sync(0xffffffffu, i2b, m);
            top2_upd(v1b, i1b, v2b, i2b, u1, j1);
            top2_upd(v1b, i1b, v2b, i2b, u2, j2);
        }
        if (tg == 0) {
            int ta = rowTok + g, tb = rowTok + g + 8;
            candV[ta * 2] = v1a; candI[ta * 2] = i1a; candV[ta * 2 + 1] = v2a; candI[ta * 2 + 1] = i2a;
            candV[tb * 2] = v1b; candI[tb * 2] = i1b; candV[tb * 2 + 1] = v2b; candI[tb * 2 + 1] = i2b;
        }
        __syncthreads();

        // ---- exact fp32 rescore of the two candidates per token ----
        {
            int t = tid >> 1, slot = tid & 1;
            int c = candI[t * 2 + slot];
            const float4* wr4 = (const float4*)(w + c * DDIM);
            float sx = 0.f, dot = 0.f;
#pragma unroll
            for (int i = 0; i < 16; i++) {
                float4 wv = wr4[i];
                float x0 = Xs[t * 65 + i * 4 + 0];
                float x1 = Xs[t * 65 + i * 4 + 1];
                float x2 = Xs[t * 65 + i * 4 + 2];
                float x3 = Xs[t * 65 + i * 4 + 3];
                sx  = fmaf(x0, x0, sx);  sx  = fmaf(x1, x1, sx);
                sx  = fmaf(x2, x2, sx);  sx  = fmaf(x3, x3, sx);
                dot = fmaf(x0, wv.x, dot); dot = fmaf(x1, wv.y, dot);
                dot = fmaf(x2, wv.z, dot); dot = fmaf(x3, wv.w, dot);
            }
            float dist = __fadd_rn(__fadd_rn(sx, -__fmul_rn(2.f, dot)), sws[c]);
            float dOth = __shfl_xor_sync(0xffffffffu, dist, 1);
            int   cOth = __shfl_xor_sync(0xffffffffu, c, 1);
            if (slot == 0) {
                int pick = better(dist, c, dOth, cOth) ? c : cOth;
                idxs[t] = pick;
                atomicAdd(&g_counts[pick], 1);
            }
        }
        __syncthreads();

        // ---- fused epilogue: out from smem x + gathered w; accumulate mse ----
        {
            size_t base4 = (size_t)T0 * 16;
            float4* out4 = (float4*)out + base4;
#pragma unroll
            for (int it = 0; it < 8; it++) {
                int q4 = it * NTHREADS + tid;         // 0..2047
                int tl = q4 >> 4, dq = q4 & 15;
                int c  = idxs[tl];
                float4 wv = ((const float4*)(w + c * DDIM))[dq];
                float x0 = Xs[tl * 65 + dq * 4 + 0];
                float x1 = Xs[tl * 65 + dq * 4 + 1];
                float x2 = Xs[tl * 65 + dq * 4 + 2];
                float x3 = Xs[tl * 65 + dq * 4 + 3];
                float d0 = wv.x - x0, d1 = wv.y - x1, d2 = wv.z - x2, d3 = wv.w - x3;
                float4 r;
                r.x = x0 + d0; r.y = x1 + d1; r.z = x2 + d2; r.w = x3 + d3;
                out4[q4] = r;
                accD += (double)d0 * d0 + (double)d1 * d1 + (double)d2 * d2 + (double)d3 * d3;
            }
        }
        // loop-top __syncthreads() protects idxs/cand/Xs reuse
    }

    // ---- one deterministic CTA reduction at the end ----
    red[tid] = accD;
    __syncthreads();
    for (int s = NTHREADS / 2; s > 0; s >>= 1) {
        if (tid < s) red[tid] += red[tid + s];
        __syncthreads();
    }
    if (tid == 0) g_partial[bid] = red[0];
}

// K2: reduce partials -> loss; counts -> perplexity
__global__ void vq_final(float* __restrict__ out, int out_size) {
    __shared__ double sA[NTHREADS];
    __shared__ double sB[NTHREADS];
    int t = threadIdx.x;
    double a = 0.0;
    for (int i = t; i < NCTAS; i += NTHREADS) a += g_partial[i];
    double b = 0.0;
    for (int i = t; i < KCODES; i += NTHREADS) {
        double p = (double)g_counts[i] / (double)N_TOK;
        b += p * log(p + 1e-10);
    }
    sA[t] = a; sB[t] = b;
    __syncthreads();
    for (int s = NTHREADS / 2; s > 0; s >>= 1) {
        if (t < s) { sA[t] += sA[t + s]; sB[t] += sB[t + s]; }
        __syncthreads();
    }
    if (t == 0) {
        double mse  = sA[0] / (double)OUT_ELEMS;
        double loss = mse + 0.25 * mse;
        double perp = exp(-sB[0]);
        if (out_size > OUT_ELEMS)     out[OUT_ELEMS]     = (float)loss;
        if (out_size > OUT_ELEMS + 1) out[OUT_ELEMS + 1] = (float)perp;
    }
}

extern "C" void kernel_launch(void* const* d_in, const int* in_sizes, int n_in,
                              void* d_out, int out_size) {
    const float* x = (const float*)d_in[0];
    const float* w = (const float*)d_in[1];
    float* out = (float*)d_out;

    cudaFuncSetAttribute(vq_main, cudaFuncAttributeMaxDynamicSharedMemorySize, SMEM_BYTES);

    vq_prep<<<16, NTHREADS>>>(w);
    vq_main<<<NCTAS, NTHREADS, SMEM_BYTES>>>(x, w, out);
    vq_final<<<1, NTHREADS>>>(out, out_size);
}